// round 5
// baseline (speedup 1.0000x reference)
#include <cuda_runtime.h>
#include <cuda_bf16.h>
#include <cstdint>

// out[t, d] = code[weight[row, d]] * absmax[row],  row = tokens[t]
// tokens [8192], weight [50400,4096] int32 codes, absmax [50400], code [256].
// Output [8192,4096] fp32. ~134 MB read + ~134 MB write.
//
// R4 -> R5: the clean conflict-free-LUT experiment. 512-thread CTAs mean
// 4 CTAs/SM = full 2048 threads while 4 x 32 KB = 128 KB smem fits -- so the
// 32x bank-replicated LUT (s[idx*32+lane], always bank==lane, conflict-free)
// now costs ZERO occupancy (R3 lost occupancy via 256-thr CTAs).
// Persistent grid (592) amortizes the 32 KB fill over ~14 tokens.

static constexpr int DIM = 4096;
static constexpr int THREADS = 512;
static constexpr int VPT = DIM / 4 / THREADS;   // 2 int4 per thread per token

__global__ __launch_bounds__(THREADS)
void bnb_embed_kernel(const int* __restrict__ tokens,
                      const int* __restrict__ weight,
                      const float* __restrict__ absmax,
                      const float* __restrict__ code,
                      float* __restrict__ out,
                      int n_tokens)
{
    // 32 replicated copies: entry i for lane l at s_code[i*32 + l].
    // bank(addr) = (i*32 + l) % 32 = l  -> conflict-free for ANY index mix.
    __shared__ float s_code[256 * 32];
    const int tid  = threadIdx.x;
    const int lane = tid & 31;
    const int wid  = tid >> 5;                 // 16 warps

    // Fill: warp w covers entries {w, w+16, ...}; each warp-STS hits all 32
    // banks (lane varies, entry fixed) -> conflict-free, 16 STS per thread.
    for (int i = wid; i < 256; i += 16) {
        s_code[i * 32 + lane] = code[i];
    }
    __syncthreads();

    const float* __restrict__ my_lut = s_code + lane;

    const int n_pairs = (n_tokens + 1) >> 1;   // 4096
    for (int p = blockIdx.x; p < n_pairs; p += gridDim.x) {
        const int tA = p * 2;
        const int tB = tA + 1;
        const bool hasB = (tB < n_tokens);

        const int rowA = __ldg(&tokens[tA]);
        const int rowB = hasB ? __ldg(&tokens[tB]) : rowA;
        const float scaleA = __ldg(&absmax[rowA]);
        const float scaleB = __ldg(&absmax[rowB]);

        const int4* __restrict__ wA =
            reinterpret_cast<const int4*>(weight + (long long)rowA * DIM);
        const int4* __restrict__ wB =
            reinterpret_cast<const int4*>(weight + (long long)rowB * DIM);
        float4* __restrict__ oA = reinterpret_cast<float4*>(out + (long long)tA * DIM);
        float4* __restrict__ oB = reinterpret_cast<float4*>(out + (long long)tB * DIM);

        // Front-batch all 4 independent 16B loads (two rows in flight).
        int4 qA[VPT], qB[VPT];
#pragma unroll
        for (int i = 0; i < VPT; i++) qA[i] = wA[tid + i * THREADS];
#pragma unroll
        for (int i = 0; i < VPT; i++) qB[i] = wB[tid + i * THREADS];

#pragma unroll
        for (int i = 0; i < VPT; i++) {
            float4 v;
            v.x = my_lut[qA[i].x << 5] * scaleA;
            v.y = my_lut[qA[i].y << 5] * scaleA;
            v.z = my_lut[qA[i].z << 5] * scaleA;
            v.w = my_lut[qA[i].w << 5] * scaleA;
            oA[tid + i * THREADS] = v;
        }
        if (hasB) {
#pragma unroll
            for (int i = 0; i < VPT; i++) {
                float4 v;
                v.x = my_lut[qB[i].x << 5] * scaleB;
                v.y = my_lut[qB[i].y << 5] * scaleB;
                v.z = my_lut[qB[i].z << 5] * scaleB;
                v.w = my_lut[qB[i].w << 5] * scaleB;
                oB[tid + i * THREADS] = v;
            }
        }
    }
}

extern "C" void kernel_launch(void* const* d_in, const int* in_sizes, int n_in,
                              void* d_out, int out_size)
{
    const int*   tokens = (const int*)d_in[0];
    const int*   weight = (const int*)d_in[1];
    const float* absmax = (const float*)d_in[2];
    const float* code   = (const float*)d_in[3];
    float*       out    = (float*)d_out;

    const int n_tokens = in_sizes[0];          // 8192
    // 4 CTAs/SM x 148 SMs; 4 x 32 KB smem = 128 KB/SM, 2048 threads/SM.
    const int grid = 4 * 148;
    bnb_embed_kernel<<<grid, THREADS>>>(tokens, weight, absmax, code, out, n_tokens);
}

// round 6
// speedup vs baseline: 1.1627x; 1.1627x over previous
#include <cuda_runtime.h>
#include <cuda_bf16.h>
#include <cstdint>

// out[t, d] = code[weight[row, d]] * absmax[row],  row = tokens[t]
// tokens [8192], weight [50400,4096] int32 codes, absmax [50400], code [256].
// Output [8192,4096] fp32. ~134 MB read + ~134 MB write, HBM-bound.
//
// R5 -> R6: revert persistent grid + replicated LUT (both regressed; LDS
// conflicts proven non-binding). Champion R4 structure (4096 one-shot CTAs,
// 512 thr, 2 tokens / 2 independent chains per CTA) + ld.global.cg on the
// zero-reuse weight stream so it stops allocating/churning L1D.

static constexpr int DIM = 4096;
static constexpr int THREADS = 512;
static constexpr int VECS = DIM / 4;          // 1024 int4 per row
static constexpr int VPT = VECS / THREADS;    // 2 int4 per thread per token

__device__ __forceinline__ int4 ldcg_int4(const int4* p) {
    int4 v;
    asm volatile("ld.global.cg.v4.b32 {%0,%1,%2,%3}, [%4];"
                 : "=r"(v.x), "=r"(v.y), "=r"(v.z), "=r"(v.w) : "l"(p));
    return v;
}

__global__ __launch_bounds__(THREADS)
void bnb_embed_kernel(const int* __restrict__ tokens,
                      const int* __restrict__ weight,
                      const float* __restrict__ absmax,
                      const float* __restrict__ code,
                      float* __restrict__ out,
                      int n_tokens)
{
    __shared__ float s_code[256];
    const int tid = threadIdx.x;
    if (tid < 256) s_code[tid] = code[tid];
    __syncthreads();

    const int tA = blockIdx.x * 2;
    const int tB = tA + 1;
    const bool hasB = (tB < n_tokens);

    const int rowA = __ldg(&tokens[tA]);
    const int rowB = hasB ? __ldg(&tokens[tB]) : rowA;
    const float scaleA = __ldg(&absmax[rowA]);
    const float scaleB = __ldg(&absmax[rowB]);

    const int4* __restrict__ wA =
        reinterpret_cast<const int4*>(weight + (long long)rowA * DIM);
    const int4* __restrict__ wB =
        reinterpret_cast<const int4*>(weight + (long long)rowB * DIM);
    float4* __restrict__ oA = reinterpret_cast<float4*>(out + (long long)tA * DIM);
    float4* __restrict__ oB = reinterpret_cast<float4*>(out + (long long)tB * DIM);

    // Front-batch all 4 independent 16B loads (two rows in flight),
    // L2-only (.cg): zero-reuse stream, keep L1D out of the way.
    int4 qA[VPT], qB[VPT];
#pragma unroll
    for (int i = 0; i < VPT; i++) qA[i] = ldcg_int4(&wA[tid + i * THREADS]);
#pragma unroll
    for (int i = 0; i < VPT; i++) qB[i] = ldcg_int4(&wB[tid + i * THREADS]);

    // Process token A while B's loads are still streaming in.
#pragma unroll
    for (int i = 0; i < VPT; i++) {
        float4 v;
        v.x = s_code[qA[i].x] * scaleA;
        v.y = s_code[qA[i].y] * scaleA;
        v.z = s_code[qA[i].z] * scaleA;
        v.w = s_code[qA[i].w] * scaleA;
        oA[tid + i * THREADS] = v;
    }
    if (hasB) {
#pragma unroll
        for (int i = 0; i < VPT; i++) {
            float4 v;
            v.x = s_code[qB[i].x] * scaleB;
            v.y = s_code[qB[i].y] * scaleB;
            v.z = s_code[qB[i].z] * scaleB;
            v.w = s_code[qB[i].w] * scaleB;
            oB[tid + i * THREADS] = v;
        }
    }
}

extern "C" void kernel_launch(void* const* d_in, const int* in_sizes, int n_in,
                              void* d_out, int out_size)
{
    const int*   tokens = (const int*)d_in[0];
    const int*   weight = (const int*)d_in[1];
    const float* absmax = (const float*)d_in[2];
    const float* code   = (const float*)d_in[3];
    float*       out    = (float*)d_out;

    const int n_tokens = in_sizes[0];        // 8192
    const int grid = (n_tokens + 1) / 2;     // 4096 one-shot CTAs
    bnb_embed_kernel<<<grid, THREADS>>>(tokens, weight, absmax, code, out, n_tokens);
}